// round 11
// baseline (speedup 1.0000x reference)
// R11: producer via cp.async.bulk + expect_tx (2 ops/thread/iter vs 9),
// relaxed producer wait, early empty-arrive. Core unchanged from R10:
// BM=128 BN=128 BK=64, 256 thr (warp 32x64), 3-stage ring, 144B pitch, 2 CTAs/SM.
#include <cuda_runtime.h>
#include <cuda_fp16.h>
#include <cstdint>

static constexpr int IN_F  = 4096;
static constexpr int OUT_F = 11008;
static constexpr int M_TOTAL = 8192;

static constexpr int BM = 128;
static constexpr int BN = 128;
static constexpr int BK = 64;
static constexpr int STAGES = 3;
static constexpr int NIT = IN_F / BK;           // 64

static constexpr int ROW_PITCH = 144;           // 128B data + 16B pad (16B-aligned for bulk)
static constexpr int A_STAGE = BM * ROW_PITCH;
static constexpr int B_STAGE = BN * ROW_PITCH;
static constexpr int STAGE_BYTES = A_STAGE + B_STAGE;               // 36864
static constexpr int SMEM_TOTAL = 128 + STAGES * STAGE_BYTES;       // 110720

static constexpr int GRID_M = M_TOTAL / BM;     // 64
static constexpr int GRID_N = OUT_F / BN;       // 86

__device__ __align__(128) __half g_wf16[(size_t)OUT_F * IN_F];    // 90 MB
__device__ __align__(128) __half g_xf16[(size_t)M_TOTAL * IN_F];  // 64 MB

// ---------------- helpers ----------------
__device__ __forceinline__ uint32_t smem_to_u32(const void* p) {
    uint32_t a;
    asm("{ .reg .u64 t; cvta.to.shared.u64 t, %1; cvt.u32.u64 %0, t; }" : "=r"(a) : "l"(p));
    return a;
}
#define MBARRIER_INIT(addr, cnt) \
    asm volatile("mbarrier.init.shared.b64 [%0], %1;" :: "r"((uint32_t)(addr)), "r"((uint32_t)(cnt)) : "memory")
#define MBARRIER_ARRIVE(addr) \
    asm volatile("mbarrier.arrive.shared.b64 _, [%0];" :: "r"((uint32_t)(addr)) : "memory")
#define MBARRIER_ARRIVE_EXPECT_TX(addr, bytes) \
    asm volatile("mbarrier.arrive.expect_tx.shared.b64 _, [%0], %1;" \
        :: "r"((uint32_t)(addr)), "r"((uint32_t)(bytes)) : "memory")
// one 128B row: global -> shared::cta, completes on mbar via tx-bytes
#define CP_BULK_ROW(dst, src, mbar) \
    asm volatile("cp.async.bulk.shared::cta.global.mbarrier::complete_tx::bytes [%0], [%1], 128, [%2];" \
        :: "r"((uint32_t)(dst)), "l"(src), "r"((uint32_t)(mbar)) : "memory")

#define MBARRIER_WAIT_PARITY(mbar_smem_addr, phase_parity) do { \
    uint32_t _mbar = (uint32_t)(mbar_smem_addr); \
    uint32_t _parity = (uint32_t)(phase_parity); \
    uint32_t _done; \
    asm volatile( \
        "{\n\t.reg .pred p;\n\t" \
        "mbarrier.try_wait.parity.acquire.cta.shared::cta.b64 p, [%1], %2;\n\t" \
        "selp.b32 %0, 1, 0, p;\n\t}" \
        : "=r"(_done) : "r"(_mbar), "r"(_parity) : "memory"); \
    if (!_done) { \
        asm volatile( \
            "{\n\t.reg .pred P1;\n\t" \
            "WAIT_LOOP_%=:\n\t" \
            "mbarrier.try_wait.parity.acquire.cta.shared::cta.b64 P1, [%0], %1, 0x989680;\n\t" \
            "@P1 bra.uni WAIT_DONE_%=;\n\t" \
            "bra.uni WAIT_LOOP_%=;\n\t" \
            "WAIT_DONE_%=:\n\t}" \
            :: "r"(_mbar), "r"(_parity) : "memory"); \
    } \
} while(0)

#define MBARRIER_WAIT_PARITY_RELAXED(mbar_smem_addr, phase_parity) do { \
    uint32_t _mbar = (uint32_t)(mbar_smem_addr); \
    uint32_t _parity = (uint32_t)(phase_parity); \
    uint32_t _done; \
    asm volatile( \
        "{\n\t.reg .pred p;\n\t" \
        "mbarrier.try_wait.parity.relaxed.cta.shared::cta.b64 p, [%1], %2;\n\t" \
        "selp.b32 %0, 1, 0, p;\n\t}" \
        : "=r"(_done) : "r"(_mbar), "r"(_parity) : "memory"); \
    if (!_done) { \
        asm volatile( \
            "{\n\t.reg .pred P1;\n\t" \
            "WAIT_LOOP_%=:\n\t" \
            "mbarrier.try_wait.parity.relaxed.cta.shared::cta.b64 P1, [%0], %1, 0x989680;\n\t" \
            "@P1 bra.uni WAIT_DONE_%=;\n\t" \
            "bra.uni WAIT_LOOP_%=;\n\t" \
            "WAIT_DONE_%=:\n\t}" \
            :: "r"(_mbar), "r"(_parity) : "memory"); \
    } \
} while(0)

#define LDSM_X4(r0, r1, r2, r3, addr) \
    asm volatile("ldmatrix.sync.aligned.m8n8.x4.shared.b16 {%0,%1,%2,%3}, [%4];" \
        : "=r"(r0), "=r"(r1), "=r"(r2), "=r"(r3) : "r"(addr))

#define MMA16816(d0, d1, d2, d3, a0, a1, a2, a3, b0, b1) \
    asm volatile("mma.sync.aligned.m16n8k16.row.col.f32.f16.f16.f32 " \
        "{%0,%1,%2,%3}, {%4,%5,%6,%7}, {%8,%9}, {%0,%1,%2,%3};" \
        : "+f"(d0), "+f"(d1), "+f"(d2), "+f"(d3) \
        : "r"(a0), "r"(a1), "r"(a2), "r"(a3), "r"(b0), "r"(b1))

// ---------------- merged pre-pass ----------------
static constexpr size_t WTOT = (size_t)OUT_F * IN_F;
static constexpr size_t XTOT = (size_t)M_TOTAL * IN_F;

__global__ void __launch_bounds__(256) convert_all_kernel(
    const int* __restrict__ qw, const float* __restrict__ x)
{
    size_t i = ((size_t)blockIdx.x * blockDim.x + threadIdx.x) * 8;
    if (i < WTOT) {
        const int4 v0 = *reinterpret_cast<const int4*>(qw + i);
        const int4 v1 = *reinterpret_cast<const int4*>(qw + i + 4);
        __half h[8];
        h[0] = __int2half_rn(v0.x); h[1] = __int2half_rn(v0.y);
        h[2] = __int2half_rn(v0.z); h[3] = __int2half_rn(v0.w);
        h[4] = __int2half_rn(v1.x); h[5] = __int2half_rn(v1.y);
        h[6] = __int2half_rn(v1.z); h[7] = __int2half_rn(v1.w);
        *reinterpret_cast<uint4*>(g_wf16 + i) = *reinterpret_cast<const uint4*>(h);
    } else {
        const size_t j = i - WTOT;
        if (j >= XTOT) return;
        const float4 v0 = *reinterpret_cast<const float4*>(x + j);
        const float4 v1 = *reinterpret_cast<const float4*>(x + j + 4);
        __half h[8];
        h[0] = __float2half_rn(v0.x); h[1] = __float2half_rn(v0.y);
        h[2] = __float2half_rn(v0.z); h[3] = __float2half_rn(v0.w);
        h[4] = __float2half_rn(v1.x); h[5] = __float2half_rn(v1.y);
        h[6] = __float2half_rn(v1.z); h[7] = __float2half_rn(v1.w);
        *reinterpret_cast<uint4*>(g_xf16 + j) = *reinterpret_cast<const uint4*>(h);
    }
}

// ---------------- main GEMM ----------------
__global__ void __launch_bounds__(256, 2) w8_gemm_kernel(
    const float* __restrict__ scale,
    const float* __restrict__ bias,
    float* __restrict__ out)
{
    extern __shared__ __align__(128) char smem_raw[];
    const uint32_t base  = smem_to_u32(smem_raw);
    const uint32_t tiles = base + 128;
    // barriers: full[s] = base + 8*s ; empty[s] = base + 24 + 8*s

    const int tid  = threadIdx.x;
    const int lane = tid & 31;
    const int wid  = tid >> 5;
    const int warp_m = wid & 3;         // 4 row groups of 32
    const int warp_n = wid >> 2;        // 2 col groups of 64

    const int m0 = blockIdx.x * BM;
    const int n0 = blockIdx.y * BN;

    if (tid == 0) {
#pragma unroll
        for (int s = 0; s < STAGES; s++) {
            MBARRIER_INIT(base + 8 * s, 256);       // full: 256 arrive.expect_tx + tx bytes
            MBARRIER_INIT(base + 24 + 8 * s, 8);    // empty: one arrive per warp
        }
    }
    __syncthreads();

    // ---- bulk-producer coords: one 128B row per thread ----
    // thread t<128 -> A row t ; t>=128 -> B row t-128
    const bool isA = tid < 128;
    const int  row = isA ? tid : tid - 128;
    const uint32_t dOff = (isA ? 0u : (uint32_t)A_STAGE) + (uint32_t)row * ROW_PITCH;
    const __half* gsrc = (isA ? g_xf16 + (size_t)(m0 + row) * IN_F
                              : g_wf16 + (size_t)(n0 + row) * IN_F);

    // ldmatrix lane addresses
    const uint32_t a_lm = (uint32_t)((warp_m * 32 + (lane & 15)) * ROW_PITCH + (lane >> 4) * 16);
    const uint32_t b_lm = (uint32_t)((warp_n * 64 + (lane & 7) + ((lane >> 4) << 3)) * ROW_PITCH
                                     + ((lane >> 3) & 1) * 16);

    float acc[2][8][4];
#pragma unroll
    for (int mi = 0; mi < 2; mi++)
#pragma unroll
        for (int ni = 0; ni < 8; ni++)
#pragma unroll
            for (int j = 0; j < 4; j++) acc[mi][ni][j] = 0.f;

    // ---- prologue: produce stages 0,1 ----
#pragma unroll
    for (int s = 0; s < STAGES - 1; s++) {
        MBARRIER_WAIT_PARITY_RELAXED(base + 24 + 8 * s, 1);
        MBARRIER_ARRIVE_EXPECT_TX(base + 8 * s, 128);
        CP_BULK_ROW(tiles + s * STAGE_BYTES + dOff, gsrc + s * BK, base + 8 * s);
    }

    int pstage = STAGES - 1, pphase = 1;   // producer cursor
    int cstage = 0,          cphase = 0;   // consumer cursor

    for (int it = 0; it < NIT; ++it) {
        // ---- consume stage cstage ----
        MBARRIER_WAIT_PARITY(base + 8 * cstage, cphase);
        const uint32_t as = tiles + cstage * STAGE_BYTES;
        const uint32_t bs = as + A_STAGE;
#pragma unroll
        for (int ks = 0; ks < 4; ks++) {
            uint32_t a[2][4];
#pragma unroll
            for (int mi = 0; mi < 2; mi++)
                LDSM_X4(a[mi][0], a[mi][1], a[mi][2], a[mi][3],
                        as + a_lm + mi * 16 * ROW_PITCH + ks * 32);
            uint32_t b[4][4];
#pragma unroll
            for (int nt = 0; nt < 4; nt++)
                LDSM_X4(b[nt][0], b[nt][1], b[nt][2], b[nt][3],
                        bs + b_lm + nt * 16 * ROW_PITCH + ks * 32);

            if (ks == 3) {
                // first MMA of last ks-group: its issue proves all this warp's
                // ldmatrix results are in registers -> stage reads complete
                MMA16816(acc[0][0][0], acc[0][0][1], acc[0][0][2], acc[0][0][3],
                         a[0][0], a[0][1], a[0][2], a[0][3], b[0][0], b[0][1]);
                if (lane == 0) MBARRIER_ARRIVE(base + 24 + 8 * cstage);
#pragma unroll
                for (int mi = 0; mi < 2; mi++)
#pragma unroll
                    for (int ni = 0; ni < 8; ni++) {
                        if (mi == 0 && ni == 0) continue;
                        MMA16816(acc[mi][ni][0], acc[mi][ni][1], acc[mi][ni][2], acc[mi][ni][3],
                                 a[mi][0], a[mi][1], a[mi][2], a[mi][3],
                                 b[ni >> 1][(ni & 1) * 2], b[ni >> 1][(ni & 1) * 2 + 1]);
                    }
            } else {
#pragma unroll
                for (int mi = 0; mi < 2; mi++)
#pragma unroll
                    for (int ni = 0; ni < 8; ni++)
                        MMA16816(acc[mi][ni][0], acc[mi][ni][1], acc[mi][ni][2], acc[mi][ni][3],
                                 a[mi][0], a[mi][1], a[mi][2], a[mi][3],
                                 b[ni >> 1][(ni & 1) * 2], b[ni >> 1][(ni & 1) * 2 + 1]);
            }
        }
        if (++cstage == STAGES) { cstage = 0; cphase ^= 1; }

        // ---- produce stage for iteration it+STAGES-1 ----
        if (it + STAGES - 1 < NIT) {
            MBARRIER_WAIT_PARITY_RELAXED(base + 24 + 8 * pstage, pphase);
            MBARRIER_ARRIVE_EXPECT_TX(base + 8 * pstage, 128);
            CP_BULK_ROW(tiles + pstage * STAGE_BYTES + dOff,
                        gsrc + (it + STAGES - 1) * BK, base + 8 * pstage);
            if (++pstage == STAGES) { pstage = 0; pphase ^= 1; }
        }
    }

    // ---- epilogue: y = round_fp16(acc*scale + bias) as float32 ----
    const int qr = lane >> 2;
    const int qc = (lane & 3) * 2;
#pragma unroll
    for (int mi = 0; mi < 2; mi++) {
#pragma unroll
        for (int half_m = 0; half_m < 2; half_m++) {
            const int m = m0 + warp_m * 32 + mi * 16 + half_m * 8 + qr;
            float* orow = out + (size_t)m * OUT_F;
#pragma unroll
            for (int ni = 0; ni < 8; ni++) {
                const int n = n0 + warp_n * 64 + ni * 8 + qc;
                const float2 s2 = *reinterpret_cast<const float2*>(scale + n);
                const float2 b2 = *reinterpret_cast<const float2*>(bias + n);
                float y0 = acc[mi][ni][half_m * 2 + 0] * s2.x + b2.x;
                float y1 = acc[mi][ni][half_m * 2 + 1] * s2.y + b2.y;
                y0 = __half2float(__float2half_rn(y0));
                y1 = __half2float(__float2half_rn(y1));
                *reinterpret_cast<float2*>(orow + n) = make_float2(y0, y1);
            }
        }
    }
}

// ---------------- launch ----------------
extern "C" void kernel_launch(void* const* d_in, const int* in_sizes, int n_in,
                              void* d_out, int out_size) {
    const float* x     = (const float*)d_in[0];
    const int*   qw    = (const int*)d_in[1];
    const float* scale = (const float*)d_in[2];
    const float* bias  = (const float*)d_in[3];
    float*       out   = (float*)d_out;

    const size_t tot8 = (WTOT + XTOT) / 8;
    convert_all_kernel<<<(int)((tot8 + 255) / 256), 256>>>(qw, x);

    cudaFuncSetAttribute(w8_gemm_kernel, cudaFuncAttributeMaxDynamicSharedMemorySize, SMEM_TOTAL);
    dim3 grid(GRID_M, GRID_N);
    w8_gemm_kernel<<<grid, 256, SMEM_TOTAL>>>(scale, bias, out);
}

// round 12
// speedup vs baseline: 1.3504x; 1.3504x over previous
// R12: tiled scratch + ONE bulk copy pair per stage (tid0 producer, expect_tx).
// Pre-pass writes A/B pre-tiled in padded smem-stage image [blk][kc][128x144B].
// Consumer core = R10 (consume-then-produce, 3-stage ring, warp 32x64, 2 CTAs/SM).
#include <cuda_runtime.h>
#include <cuda_fp16.h>
#include <cstdint>

static constexpr int IN_F  = 4096;
static constexpr int OUT_F = 11008;
static constexpr int M_TOTAL = 8192;

static constexpr int BM = 128;
static constexpr int BN = 128;
static constexpr int BK = 64;
static constexpr int STAGES = 3;
static constexpr int NIT = IN_F / BK;           // 64
static constexpr int K_BLKS = NIT;              // 64
static constexpr int M_BLKS = M_TOTAL / BM;     // 64
static constexpr int N_BLKS = OUT_F / BN;       // 86

static constexpr int ROW_PITCH = 144;           // 128B data + 16B pad
static constexpr int ROW_HALFS = ROW_PITCH / 2; // 72
static constexpr int CHUNK_HALFS = 128 * ROW_HALFS;       // 9216 halfs = 18432 B
static constexpr int A_STAGE = BM * ROW_PITCH;            // 18432
static constexpr int STAGE_BYTES = 2 * A_STAGE;           // 36864
static constexpr int SMEM_TOTAL = 128 + STAGES * STAGE_BYTES;  // 110720

// pre-tiled padded scratch (device globals — no allocation APIs)
__device__ __align__(128) __half g_wt[(size_t)N_BLKS * K_BLKS * CHUNK_HALFS];  // 101.4 MB
__device__ __align__(128) __half g_xt[(size_t)M_BLKS * K_BLKS * CHUNK_HALFS];  //  75.5 MB

// ---------------- helpers ----------------
__device__ __forceinline__ uint32_t smem_to_u32(const void* p) {
    uint32_t a;
    asm("{ .reg .u64 t; cvta.to.shared.u64 t, %1; cvt.u32.u64 %0, t; }" : "=r"(a) : "l"(p));
    return a;
}
#define MBARRIER_INIT(addr, cnt) \
    asm volatile("mbarrier.init.shared.b64 [%0], %1;" :: "r"((uint32_t)(addr)), "r"((uint32_t)(cnt)) : "memory")
#define MBARRIER_ARRIVE(addr) \
    asm volatile("mbarrier.arrive.shared.b64 _, [%0];" :: "r"((uint32_t)(addr)) : "memory")
#define MBARRIER_ARRIVE_EXPECT_TX(addr, bytes) \
    asm volatile("mbarrier.arrive.expect_tx.shared.b64 _, [%0], %1;" \
        :: "r"((uint32_t)(addr)), "r"((uint32_t)(bytes)) : "memory")
#define CP_BULK(dst, src, nbytes, mbar) \
    asm volatile("cp.async.bulk.shared::cta.global.mbarrier::complete_tx::bytes [%0], [%1], %2, [%3];" \
        :: "r"((uint32_t)(dst)), "l"(src), "r"((uint32_t)(nbytes)), "r"((uint32_t)(mbar)) : "memory")

#define MBARRIER_WAIT_PARITY(mbar_smem_addr, phase_parity) do { \
    uint32_t _mbar = (uint32_t)(mbar_smem_addr); \
    uint32_t _parity = (uint32_t)(phase_parity); \
    uint32_t _done; \
    asm volatile( \
        "{\n\t.reg .pred p;\n\t" \
        "mbarrier.try_wait.parity.acquire.cta.shared::cta.b64 p, [%1], %2;\n\t" \
        "selp.b32 %0, 1, 0, p;\n\t}" \
        : "=r"(_done) : "r"(_mbar), "r"(_parity) : "memory"); \
    if (!_done) { \
        asm volatile( \
            "{\n\t.reg .pred P1;\n\t" \
            "WAIT_LOOP_%=:\n\t" \
            "mbarrier.try_wait.parity.acquire.cta.shared::cta.b64 P1, [%0], %1, 0x989680;\n\t" \
            "@P1 bra.uni WAIT_DONE_%=;\n\t" \
            "bra.uni WAIT_LOOP_%=;\n\t" \
            "WAIT_DONE_%=:\n\t}" \
            :: "r"(_mbar), "r"(_parity) : "memory"); \
    } \
} while(0)

#define MBARRIER_WAIT_PARITY_RELAXED(mbar_smem_addr, phase_parity) do { \
    uint32_t _mbar = (uint32_t)(mbar_smem_addr); \
    uint32_t _parity = (uint32_t)(phase_parity); \
    uint32_t _done; \
    asm volatile( \
        "{\n\t.reg .pred p;\n\t" \
        "mbarrier.try_wait.parity.relaxed.cta.shared::cta.b64 p, [%1], %2;\n\t" \
        "selp.b32 %0, 1, 0, p;\n\t}" \
        : "=r"(_done) : "r"(_mbar), "r"(_parity) : "memory"); \
    if (!_done) { \
        asm volatile( \
            "{\n\t.reg .pred P1;\n\t" \
            "WAIT_LOOP_%=:\n\t" \
            "mbarrier.try_wait.parity.relaxed.cta.shared::cta.b64 P1, [%0], %1, 0x989680;\n\t" \
            "@P1 bra.uni WAIT_DONE_%=;\n\t" \
            "bra.uni WAIT_LOOP_%=;\n\t" \
            "WAIT_DONE_%=:\n\t}" \
            :: "r"(_mbar), "r"(_parity) : "memory"); \
    } \
} while(0)

#define LDSM_X4(r0, r1, r2, r3, addr) \
    asm volatile("ldmatrix.sync.aligned.m8n8.x4.shared.b16 {%0,%1,%2,%3}, [%4];" \
        : "=r"(r0), "=r"(r1), "=r"(r2), "=r"(r3) : "r"(addr))

#define MMA16816(d0, d1, d2, d3, a0, a1, a2, a3, b0, b1) \
    asm volatile("mma.sync.aligned.m16n8k16.row.col.f32.f16.f16.f32 " \
        "{%0,%1,%2,%3}, {%4,%5,%6,%7}, {%8,%9}, {%0,%1,%2,%3};" \
        : "+f"(d0), "+f"(d1), "+f"(d2), "+f"(d3) \
        : "r"(a0), "r"(a1), "r"(a2), "r"(a3), "r"(b0), "r"(b1))

// ---------------- pre-pass: convert AND tile into padded stage images ----------------
static constexpr size_t WTOT = (size_t)OUT_F * IN_F;
static constexpr size_t XTOT = (size_t)M_TOTAL * IN_F;

__global__ void __launch_bounds__(256) convert_all_kernel(
    const int* __restrict__ qw, const float* __restrict__ x)
{
    size_t i = ((size_t)blockIdx.x * blockDim.x + threadIdx.x) * 8;
    if (i < WTOT) {
        const int o = (int)(i / IN_F), icol = (int)(i % IN_F);
        const int4 v0 = *reinterpret_cast<const int4*>(qw + i);
        const int4 v1 = *reinterpret_cast<const int4*>(qw + i + 4);
        __half h[8];
        h[0] = __int2half_rn(v0.x); h[1] = __int2half_rn(v0.y);
        h[2] = __int2half_rn(v0.z); h[3] = __int2half_rn(v0.w);
        h[4] = __int2half_rn(v1.x); h[5] = __int2half_rn(v1.y);
        h[6] = __int2half_rn(v1.z); h[7] = __int2half_rn(v1.w);
        // tiled dest: [(n_blk*K_BLKS + k_blk)] chunk, row = o&127, col = icol&63
        const size_t dst = ((size_t)((o >> 7) * K_BLKS + (icol >> 6)) * 128 + (o & 127)) * ROW_HALFS
                           + (icol & 63);
        *reinterpret_cast<uint4*>(g_wt + dst) = *reinterpret_cast<const uint4*>(h);
    } else {
        const size_t j = i - WTOT;
        if (j >= XTOT) return;
        const int m = (int)(j / IN_F), icol = (int)(j % IN_F);
        const float4 v0 = *reinterpret_cast<const float4*>(x + j);
        const float4 v1 = *reinterpret_cast<const float4*>(x + j + 4);
        __half h[8];
        h[0] = __float2half_rn(v0.x); h[1] = __float2half_rn(v0.y);
        h[2] = __float2half_rn(v0.z); h[3] = __float2half_rn(v0.w);
        h[4] = __float2half_rn(v1.x); h[5] = __float2half_rn(v1.y);
        h[6] = __float2half_rn(v1.z); h[7] = __float2half_rn(v1.w);
        const size_t dst = ((size_t)((m >> 7) * K_BLKS + (icol >> 6)) * 128 + (m & 127)) * ROW_HALFS
                           + (icol & 63);
        *reinterpret_cast<uint4*>(g_xt + dst) = *reinterpret_cast<const uint4*>(h);
    }
}

// ---------------- main GEMM ----------------
__global__ void __launch_bounds__(256, 2) w8_gemm_kernel(
    const float* __restrict__ scale,
    const float* __restrict__ bias,
    float* __restrict__ out)
{
    extern __shared__ __align__(128) char smem_raw[];
    const uint32_t base  = smem_to_u32(smem_raw);
    const uint32_t tiles = base + 128;
    // barriers: full[s] = base + 8*s ; empty[s] = base + 24 + 8*s

    const int tid  = threadIdx.x;
    const int lane = tid & 31;
    const int wid  = tid >> 5;
    const int warp_m = wid & 3;         // 4 row groups of 32
    const int warp_n = wid >> 2;        // 2 col groups of 64

    if (tid == 0) {
#pragma unroll
        for (int s = 0; s < STAGES; s++) {
            MBARRIER_INIT(base + 8 * s, 1);         // full: tid0's expect_tx arrive + tx bytes
            MBARRIER_INIT(base + 24 + 8 * s, 8);    // empty: one arrive per warp
        }
    }
    __syncthreads();

    // pre-tiled global sources (one contiguous 18432B chunk per k-step)
    const __half* gA_tile = g_xt + (size_t)blockIdx.x * K_BLKS * CHUNK_HALFS;
    const __half* gB_tile = g_wt + (size_t)blockIdx.y * K_BLKS * CHUNK_HALFS;

    // ldmatrix lane addresses
    const uint32_t a_lm = (uint32_t)((warp_m * 32 + (lane & 15)) * ROW_PITCH + (lane >> 4) * 16);
    const uint32_t b_lm = (uint32_t)((warp_n * 64 + (lane & 7) + ((lane >> 4) << 3)) * ROW_PITCH
                                     + ((lane >> 3) & 1) * 16);

    float acc[2][8][4];
#pragma unroll
    for (int mi = 0; mi < 2; mi++)
#pragma unroll
        for (int ni = 0; ni < 8; ni++)
#pragma unroll
            for (int j = 0; j < 4; j++) acc[mi][ni][j] = 0.f;

    // ---- prologue: tid0 produces stages 0,1 ----
    if (tid == 0) {
#pragma unroll
        for (int s = 0; s < STAGES - 1; s++) {
            MBARRIER_WAIT_PARITY_RELAXED(base + 24 + 8 * s, 1);
            MBARRIER_ARRIVE_EXPECT_TX(base + 8 * s, STAGE_BYTES);
            const uint32_t st = tiles + s * STAGE_BYTES;
            CP_BULK(st,           gA_tile + (size_t)s * CHUNK_HALFS, A_STAGE, base + 8 * s);
            CP_BULK(st + A_STAGE, gB_tile + (size_t)s * CHUNK_HALFS, A_STAGE, base + 8 * s);
        }
    }

    int pstage = STAGES - 1, pphase = 1;   // producer cursor (tid0 only)
    int cstage = 0,          cphase = 0;   // consumer cursor

    for (int it = 0; it < NIT; ++it) {
        // ---- consume stage cstage ----
        MBARRIER_WAIT_PARITY(base + 8 * cstage, cphase);
        const uint32_t as = tiles + cstage * STAGE_BYTES;
        const uint32_t bs = as + A_STAGE;
#pragma unroll
        for (int ks = 0; ks < 4; ks++) {
            uint32_t a[2][4];
#pragma unroll
            for (int mi = 0; mi < 2; mi++)
                LDSM_X4(a[mi][0], a[mi][1], a[mi][2], a[mi][3],
                        as + a_lm + mi * 16 * ROW_PITCH + ks * 32);
            uint32_t b[4][4];
#pragma unroll
            for (int nt = 0; nt < 4; nt++)
                LDSM_X4(b[nt][0], b[nt][1], b[nt][2], b[nt][3],
                        bs + b_lm + nt * 16 * ROW_PITCH + ks * 32);
#pragma unroll
            for (int mi = 0; mi < 2; mi++)
#pragma unroll
                for (int ni = 0; ni < 8; ni++)
                    MMA16816(acc[mi][ni][0], acc[mi][ni][1], acc[mi][ni][2], acc[mi][ni][3],
                             a[mi][0], a[mi][1], a[mi][2], a[mi][3],
                             b[ni >> 1][(ni & 1) * 2], b[ni >> 1][(ni & 1) * 2 + 1]);
        }
        if (lane == 0) MBARRIER_ARRIVE(base + 24 + 8 * cstage);
        if (++cstage == STAGES) { cstage = 0; cphase ^= 1; }

        // ---- tid0 produces stage for iteration it+STAGES-1 ----
        if (tid == 0 && it + STAGES - 1 < NIT) {
            MBARRIER_WAIT_PARITY_RELAXED(base + 24 + 8 * pstage, pphase);
            MBARRIER_ARRIVE_EXPECT_TX(base + 8 * pstage, STAGE_BYTES);
            const uint32_t st = tiles + pstage * STAGE_BYTES;
            const size_t kc = (size_t)(it + STAGES - 1) * CHUNK_HALFS;
            CP_BULK(st,           gA_tile + kc, A_STAGE, base + 8 * pstage);
            CP_BULK(st + A_STAGE, gB_tile + kc, A_STAGE, base + 8 * pstage);
        }
        if (++pstage == STAGES) { pstage = 0; pphase ^= 1; }
    }

    // ---- epilogue: y = round_fp16(acc*scale + bias) as float32 ----
    const int m0 = blockIdx.x * BM;
    const int n0 = blockIdx.y * BN;
    const int qr = lane >> 2;
    const int qc = (lane & 3) * 2;
#pragma unroll
    for (int mi = 0; mi < 2; mi++) {
#pragma unroll
        for (int half_m = 0; half_m < 2; half_m++) {
            const int m = m0 + warp_m * 32 + mi * 16 + half_m * 8 + qr;
            float* orow = out + (size_t)m * OUT_F;
#pragma unroll
            for (int ni = 0; ni < 8; ni++) {
                const int n = n0 + warp_n * 64 + ni * 8 + qc;
                const float2 s2 = *reinterpret_cast<const float2*>(scale + n);
                const float2 b2 = *reinterpret_cast<const float2*>(bias + n);
                float y0 = acc[mi][ni][half_m * 2 + 0] * s2.x + b2.x;
                float y1 = acc[mi][ni][half_m * 2 + 1] * s2.y + b2.y;
                y0 = __half2float(__float2half_rn(y0));
                y1 = __half2float(__float2half_rn(y1));
                *reinterpret_cast<float2*>(orow + n) = make_float2(y0, y1);
            }
        }
    }
}

// ---------------- launch ----------------
extern "C" void kernel_launch(void* const* d_in, const int* in_sizes, int n_in,
                              void* d_out, int out_size) {
    const float* x     = (const float*)d_in[0];
    const int*   qw    = (const int*)d_in[1];
    const float* scale = (const float*)d_in[2];
    const float* bias  = (const float*)d_in[3];
    float*       out   = (float*)d_out;

    const size_t tot8 = (WTOT + XTOT) / 8;
    convert_all_kernel<<<(int)((tot8 + 255) / 256), 256>>>(qw, x);

    cudaFuncSetAttribute(w8_gemm_kernel, cudaFuncAttributeMaxDynamicSharedMemorySize, SMEM_TOTAL);
    dim3 grid(M_BLKS, N_BLKS);
    w8_gemm_kernel<<<grid, 256, SMEM_TOTAL>>>(scale, bias, out);
}

// round 13
// speedup vs baseline: 1.3623x; 1.0088x over previous
// R13: warp tile 64x64 (128 thr, 4 warps) on the R12 pipeline — halves LDSM
// bytes per FLOP (crossbar floor 2060->1560 cyc), tensor pipe becomes sole floor.
// BM=128 BN=128 BK=64, 3-stage ring, tid0 bulk producer, 144B pitch, 2 CTAs/SM.
#include <cuda_runtime.h>
#include <cuda_fp16.h>
#include <cstdint>

static constexpr int IN_F  = 4096;
static constexpr int OUT_F = 11008;
static constexpr int M_TOTAL = 8192;

static constexpr int BM = 128;
static constexpr int BN = 128;
static constexpr int BK = 64;
static constexpr int STAGES = 3;
static constexpr int NIT = IN_F / BK;           // 64
static constexpr int K_BLKS = NIT;              // 64
static constexpr int M_BLKS = M_TOTAL / BM;     // 64
static constexpr int N_BLKS = OUT_F / BN;       // 86

static constexpr int ROW_PITCH = 144;           // 128B data + 16B pad
static constexpr int ROW_HALFS = ROW_PITCH / 2; // 72
static constexpr int CHUNK_HALFS = 128 * ROW_HALFS;       // 18432 B
static constexpr int A_STAGE = BM * ROW_PITCH;            // 18432
static constexpr int STAGE_BYTES = 2 * A_STAGE;           // 36864
static constexpr int SMEM_TOTAL = 128 + STAGES * STAGE_BYTES;  // 110720

// pre-tiled padded scratch
__device__ __align__(128) __half g_wt[(size_t)N_BLKS * K_BLKS * CHUNK_HALFS];
__device__ __align__(128) __half g_xt[(size_t)M_BLKS * K_BLKS * CHUNK_HALFS];

// ---------------- helpers ----------------
__device__ __forceinline__ uint32_t smem_to_u32(const void* p) {
    uint32_t a;
    asm("{ .reg .u64 t; cvta.to.shared.u64 t, %1; cvt.u32.u64 %0, t; }" : "=r"(a) : "l"(p));
    return a;
}
#define MBARRIER_INIT(addr, cnt) \
    asm volatile("mbarrier.init.shared.b64 [%0], %1;" :: "r"((uint32_t)(addr)), "r"((uint32_t)(cnt)) : "memory")
#define MBARRIER_ARRIVE(addr) \
    asm volatile("mbarrier.arrive.shared.b64 _, [%0];" :: "r"((uint32_t)(addr)) : "memory")
#define MBARRIER_ARRIVE_EXPECT_TX(addr, bytes) \
    asm volatile("mbarrier.arrive.expect_tx.shared.b64 _, [%0], %1;" \
        :: "r"((uint32_t)(addr)), "r"((uint32_t)(bytes)) : "memory")
#define CP_BULK(dst, src, nbytes, mbar) \
    asm volatile("cp.async.bulk.shared::cta.global.mbarrier::complete_tx::bytes [%0], [%1], %2, [%3];" \
        :: "r"((uint32_t)(dst)), "l"(src), "r"((uint32_t)(nbytes)), "r"((uint32_t)(mbar)) : "memory")

#define MBARRIER_WAIT_PARITY(mbar_smem_addr, phase_parity) do { \
    uint32_t _mbar = (uint32_t)(mbar_smem_addr); \
    uint32_t _parity = (uint32_t)(phase_parity); \
    uint32_t _done; \
    asm volatile( \
        "{\n\t.reg .pred p;\n\t" \
        "mbarrier.try_wait.parity.acquire.cta.shared::cta.b64 p, [%1], %2;\n\t" \
        "selp.b32 %0, 1, 0, p;\n\t}" \
        : "=r"(_done) : "r"(_mbar), "r"(_parity) : "memory"); \
    if (!_done) { \
        asm volatile( \
            "{\n\t.reg .pred P1;\n\t" \
            "WAIT_LOOP_%=:\n\t" \
            "mbarrier.try_wait.parity.acquire.cta.shared::cta.b64 P1, [%0], %1, 0x989680;\n\t" \
            "@P1 bra.uni WAIT_DONE_%=;\n\t" \
            "bra.uni WAIT_LOOP_%=;\n\t" \
            "WAIT_DONE_%=:\n\t}" \
            :: "r"(_mbar), "r"(_parity) : "memory"); \
    } \
} while(0)

#define MBARRIER_WAIT_PARITY_RELAXED(mbar_smem_addr, phase_parity) do { \
    uint32_t _mbar = (uint32_t)(mbar_smem_addr); \
    uint32_t _parity = (uint32_t)(phase_parity); \
    uint32_t _done; \
    asm volatile( \
        "{\n\t.reg .pred p;\n\t" \
        "mbarrier.try_wait.parity.relaxed.cta.shared::cta.b64 p, [%1], %2;\n\t" \
        "selp.b32 %0, 1, 0, p;\n\t}" \
        : "=r"(_done) : "r"(_mbar), "r"(_parity) : "memory"); \
    if (!_done) { \
        asm volatile( \
            "{\n\t.reg .pred P1;\n\t" \
            "WAIT_LOOP_%=:\n\t" \
            "mbarrier.try_wait.parity.relaxed.cta.shared::cta.b64 P1, [%0], %1, 0x989680;\n\t" \
            "@P1 bra.uni WAIT_DONE_%=;\n\t" \
            "bra.uni WAIT_LOOP_%=;\n\t" \
            "WAIT_DONE_%=:\n\t}" \
            :: "r"(_mbar), "r"(_parity) : "memory"); \
    } \
} while(0)

#define LDSM_X4(r0, r1, r2, r3, addr) \
    asm volatile("ldmatrix.sync.aligned.m8n8.x4.shared.b16 {%0,%1,%2,%3}, [%4];" \
        : "=r"(r0), "=r"(r1), "=r"(r2), "=r"(r3) : "r"(addr))

#define MMA16816(d0, d1, d2, d3, a0, a1, a2, a3, b0, b1) \
    asm volatile("mma.sync.aligned.m16n8k16.row.col.f32.f16.f16.f32 " \
        "{%0,%1,%2,%3}, {%4,%5,%6,%7}, {%8,%9}, {%0,%1,%2,%3};" \
        : "+f"(d0), "+f"(d1), "+f"(d2), "+f"(d3) \
        : "r"(a0), "r"(a1), "r"(a2), "r"(a3), "r"(b0), "r"(b1))

// ---------------- pre-pass: convert AND tile into padded stage images ----------------
static constexpr size_t WTOT = (size_t)OUT_F * IN_F;
static constexpr size_t XTOT = (size_t)M_TOTAL * IN_F;

__global__ void __launch_bounds__(256) convert_all_kernel(
    const int* __restrict__ qw, const float* __restrict__ x)
{
    size_t i = ((size_t)blockIdx.x * blockDim.x + threadIdx.x) * 8;
    if (i < WTOT) {
        const int o = (int)(i / IN_F), icol = (int)(i % IN_F);
        const int4 v0 = *reinterpret_cast<const int4*>(qw + i);
        const int4 v1 = *reinterpret_cast<const int4*>(qw + i + 4);
        __half h[8];
        h[0] = __int2half_rn(v0.x); h[1] = __int2half_rn(v0.y);
        h[2] = __int2half_rn(v0.z); h[3] = __int2half_rn(v0.w);
        h[4] = __int2half_rn(v1.x); h[5] = __int2half_rn(v1.y);
        h[6] = __int2half_rn(v1.z); h[7] = __int2half_rn(v1.w);
        const size_t dst = ((size_t)((o >> 7) * K_BLKS + (icol >> 6)) * 128 + (o & 127)) * ROW_HALFS
                           + (icol & 63);
        *reinterpret_cast<uint4*>(g_wt + dst) = *reinterpret_cast<const uint4*>(h);
    } else {
        const size_t j = i - WTOT;
        if (j >= XTOT) return;
        const int m = (int)(j / IN_F), icol = (int)(j % IN_F);
        const float4 v0 = *reinterpret_cast<const float4*>(x + j);
        const float4 v1 = *reinterpret_cast<const float4*>(x + j + 4);
        __half h[8];
        h[0] = __float2half_rn(v0.x); h[1] = __float2half_rn(v0.y);
        h[2] = __float2half_rn(v0.z); h[3] = __float2half_rn(v0.w);
        h[4] = __float2half_rn(v1.x); h[5] = __float2half_rn(v1.y);
        h[6] = __float2half_rn(v1.z); h[7] = __float2half_rn(v1.w);
        const size_t dst = ((size_t)((m >> 7) * K_BLKS + (icol >> 6)) * 128 + (m & 127)) * ROW_HALFS
                           + (icol & 63);
        *reinterpret_cast<uint4*>(g_xt + dst) = *reinterpret_cast<const uint4*>(h);
    }
}

// ---------------- main GEMM ----------------
__global__ void __launch_bounds__(128, 2) w8_gemm_kernel(
    const float* __restrict__ scale,
    const float* __restrict__ bias,
    float* __restrict__ out)
{
    extern __shared__ __align__(128) char smem_raw[];
    const uint32_t base  = smem_to_u32(smem_raw);
    const uint32_t tiles = base + 128;
    // barriers: full[s] = base + 8*s ; empty[s] = base + 24 + 8*s

    const int tid  = threadIdx.x;
    const int lane = tid & 31;
    const int wid  = tid >> 5;
    const int warp_m = wid & 1;         // 2 row groups of 64
    const int warp_n = wid >> 1;        // 2 col groups of 64

    if (tid == 0) {
#pragma unroll
        for (int s = 0; s < STAGES; s++) {
            MBARRIER_INIT(base + 8 * s, 1);         // full: tid0 expect_tx + tx bytes
            MBARRIER_INIT(base + 24 + 8 * s, 4);    // empty: one arrive per warp
        }
    }
    __syncthreads();

    const __half* gA_tile = g_xt + (size_t)blockIdx.x * K_BLKS * CHUNK_HALFS;
    const __half* gB_tile = g_wt + (size_t)blockIdx.y * K_BLKS * CHUNK_HALFS;

    // ldmatrix lane addresses (64x64 warp tile)
    const uint32_t a_lm = (uint32_t)((warp_m * 64 + (lane & 15)) * ROW_PITCH + (lane >> 4) * 16);
    const uint32_t b_lm = (uint32_t)((warp_n * 64 + (lane & 7) + ((lane >> 4) << 3)) * ROW_PITCH
                                     + ((lane >> 3) & 1) * 16);

    float acc[4][8][4];
#pragma unroll
    for (int mi = 0; mi < 4; mi++)
#pragma unroll
        for (int ni = 0; ni < 8; ni++)
#pragma unroll
            for (int j = 0; j < 4; j++) acc[mi][ni][j] = 0.f;

    // ---- prologue: tid0 produces stages 0,1 ----
    if (tid == 0) {
#pragma unroll
        for (int s = 0; s < STAGES - 1; s++) {
            MBARRIER_WAIT_PARITY_RELAXED(base + 24 + 8 * s, 1);
            MBARRIER_ARRIVE_EXPECT_TX(base + 8 * s, STAGE_BYTES);
            const uint32_t st = tiles + s * STAGE_BYTES;
            CP_BULK(st,           gA_tile + (size_t)s * CHUNK_HALFS, A_STAGE, base + 8 * s);
            CP_BULK(st + A_STAGE, gB_tile + (size_t)s * CHUNK_HALFS, A_STAGE, base + 8 * s);
        }
    }

    int pstage = STAGES - 1, pphase = 1;   // producer cursor (tid0 only)
    int cstage = 0,          cphase = 0;   // consumer cursor

    for (int it = 0; it < NIT; ++it) {
        // ---- consume stage cstage ----
        MBARRIER_WAIT_PARITY(base + 8 * cstage, cphase);
        const uint32_t as = tiles + cstage * STAGE_BYTES;
        const uint32_t bs = as + A_STAGE;
#pragma unroll
        for (int ks = 0; ks < 4; ks++) {
            uint32_t a[4][4];
#pragma unroll
            for (int mi = 0; mi < 4; mi++)
                LDSM_X4(a[mi][0], a[mi][1], a[mi][2], a[mi][3],
                        as + a_lm + mi * 16 * ROW_PITCH + ks * 32);
            uint32_t b[4][4];
#pragma unroll
            for (int nt = 0; nt < 4; nt++)
                LDSM_X4(b[nt][0], b[nt][1], b[nt][2], b[nt][3],
                        bs + b_lm + nt * 16 * ROW_PITCH + ks * 32);
#pragma unroll
            for (int mi = 0; mi < 4; mi++)
#pragma unroll
                for (int ni = 0; ni < 8; ni++)
                    MMA16816(acc[mi][ni][0], acc[mi][ni][1], acc[mi][ni][2], acc[mi][ni][3],
                             a[mi][0], a[mi][1], a[mi][2], a[mi][3],
                             b[ni >> 1][(ni & 1) * 2], b[ni >> 1][(ni & 1) * 2 + 1]);
        }
        if (lane == 0) MBARRIER_ARRIVE(base + 24 + 8 * cstage);
        if (++cstage == STAGES) { cstage = 0; cphase ^= 1; }

        // ---- tid0 produces stage for iteration it+STAGES-1 ----
        if (tid == 0 && it + STAGES - 1 < NIT) {
            MBARRIER_WAIT_PARITY_RELAXED(base + 24 + 8 * pstage, pphase);
            MBARRIER_ARRIVE_EXPECT_TX(base + 8 * pstage, STAGE_BYTES);
            const uint32_t st = tiles + pstage * STAGE_BYTES;
            const size_t kc = (size_t)(it + STAGES - 1) * CHUNK_HALFS;
            CP_BULK(st,           gA_tile + kc, A_STAGE, base + 8 * pstage);
            CP_BULK(st + A_STAGE, gB_tile + kc, A_STAGE, base + 8 * pstage);
        }
        if (++pstage == STAGES) { pstage = 0; pphase ^= 1; }
    }

    // ---- epilogue: y = round_fp16(acc*scale + bias) as float32 ----
    const int m0 = blockIdx.x * BM;
    const int n0 = blockIdx.y * BN;
    const int qr = lane >> 2;
    const int qc = (lane & 3) * 2;
#pragma unroll
    for (int mi = 0; mi < 4; mi++) {
#pragma unroll
        for (int half_m = 0; half_m < 2; half_m++) {
            const int m = m0 + warp_m * 64 + mi * 16 + half_m * 8 + qr;
            float* orow = out + (size_t)m * OUT_F;
#pragma unroll
            for (int ni = 0; ni < 8; ni++) {
                const int n = n0 + warp_n * 64 + ni * 8 + qc;
                const float2 s2 = *reinterpret_cast<const float2*>(scale + n);
                const float2 b2 = *reinterpret_cast<const float2*>(bias + n);
                float y0 = acc[mi][ni][half_m * 2 + 0] * s2.x + b2.x;
                float y1 = acc[mi][ni][half_m * 2 + 1] * s2.y + b2.y;
                y0 = __half2float(__float2half_rn(y0));
                y1 = __half2float(__float2half_rn(y1));
                *reinterpret_cast<float2*>(orow + n) = make_float2(y0, y1);
            }
        }
    }
}

// ---------------- launch ----------------
extern "C" void kernel_launch(void* const* d_in, const int* in_sizes, int n_in,
                              void* d_out, int out_size) {
    const float* x     = (const float*)d_in[0];
    const int*   qw    = (const int*)d_in[1];
    const float* scale = (const float*)d_in[2];
    const float* bias  = (const float*)d_in[3];
    float*       out   = (float*)d_out;

    const size_t tot8 = (WTOT + XTOT) / 8;
    convert_all_kernel<<<(int)((tot8 + 255) / 256), 256>>>(qw, x);

    cudaFuncSetAttribute(w8_gemm_kernel, cudaFuncAttributeMaxDynamicSharedMemorySize, SMEM_TOTAL);
    dim3 grid(M_BLKS, N_BLKS);
    w8_gemm_kernel<<<grid, 128, SMEM_TOTAL>>>(scale, bias, out);
}